// round 9
// baseline (speedup 1.0000x reference)
#include <cuda_runtime.h>
#include <math.h>

#define BB 2
#define NN 8192
#define DD 64
#define KNBR 16
#define NPTS (BB*NN)          // 16384
#define ROWS (NPTS*KNBR)      // 262144

// ---- spatial grid for KNN (Morton-ordered cells) ----
#define GD   64
#define GD3  (GD*GD*GD)       // 262144
#define CPT  256              // cells per scan thread (1024*256 == GD3)
#define XMIN (-8.0f)
#define HCELL 0.25f
#define INVH  4.0f

// ---------------- scratch (static device arrays; no allocation) ----------------
__device__ float  g_q  [NPTS*DD];
__device__ float  g_kf [NPTS*DD];
__device__ float  g_vf [NPTS*DD];
__device__ int    g_knn[ROWS];
__device__ float  g_res[NPTS*DD];
__device__ float  g_sum[DD];
__device__ float  g_sumsq[DD];
__device__ int    g_cnt  [BB*GD3];
__device__ int    g_start[BB*(GD3+1)];
__device__ int    g_cur  [BB*GD3];
__device__ float4 g_pts  [NPTS];     // Morton-cell-sorted (x,y,z,|p|^2) per batch
__device__ int    g_sid  [NPTS];     // original index of sorted point

// ---------------- packed f32x2 helpers ----------------
__device__ __forceinline__ void fma2(unsigned long long &d, unsigned long long a, unsigned long long b) {
    asm("fma.rn.f32x2 %0, %1, %2, %0;" : "+l"(d) : "l"(a), "l"(b));
}
__device__ __forceinline__ unsigned long long pk2(float lo, float hi) {
    unsigned long long r; asm("mov.b64 %0, {%1,%2};" : "=l"(r) : "f"(lo), "f"(hi)); return r;
}
__device__ __forceinline__ float2 up2(unsigned long long v) {
    float2 r; asm("mov.b64 {%0,%1}, %2;" : "=f"(r.x), "=f"(r.y) : "l"(v)); return r;
}

// 128x64 GEMM slice. sA: k-major [64][132]; sW: row-major [64][64].
__device__ __forceinline__ void gemm_f32x2(const float* __restrict__ sA, const float* __restrict__ sW,
                                           int mbase, int c0,
                                           unsigned long long* a0, unsigned long long* a1)
{
    #pragma unroll 4
    for (int kk = 0; kk < 64; kk++) {
        const ulonglong2* ap = (const ulonglong2*)(sA + kk*132 + mbase);   // broadcast LDS.128
        float2 w = *(const float2*)(sW + kk*64 + c0);                      // LDS.64
        unsigned long long w0 = pk2(w.x, w.x);
        unsigned long long w1 = pk2(w.y, w.y);
        ulonglong2 A0 = ap[0], A1 = ap[1];
        fma2(a0[0], A0.x, w0); fma2(a1[0], A0.x, w1);
        fma2(a0[1], A0.y, w0); fma2(a1[1], A0.y, w1);
        fma2(a0[2], A1.x, w0); fma2(a1[2], A1.x, w1);
        fma2(a0[3], A1.y, w0); fma2(a1[3], A1.y, w1);
        ulonglong2 A2 = ap[2], A3 = ap[3];
        fma2(a0[4], A2.x, w0); fma2(a1[4], A2.x, w1);
        fma2(a0[5], A2.y, w0); fma2(a1[5], A2.y, w1);
        fma2(a0[6], A3.x, w0); fma2(a1[6], A3.x, w1);
        fma2(a0[7], A3.y, w0); fma2(a1[7], A3.y, w1);
    }
}

// ---------------- morton helpers ----------------
__device__ __forceinline__ unsigned spread6(unsigned x) {
    x &= 0x3Fu;
    x = (x | (x << 16)) & 0x030000FFu;
    x = (x | (x <<  8)) & 0x0300F00Fu;
    x = (x | (x <<  4)) & 0x030C30C3u;
    x = (x | (x <<  2)) & 0x09249249u;
    return x;
}
__device__ __forceinline__ int cellCoord(float v) {
    int c = (int)((v - XMIN) * INVH);
    return min(max(c, 0), GD-1);
}
__device__ __forceinline__ int mortonOf(int cx, int cy, int cz) {
    return (int)(spread6(cx) | (spread6(cy) << 1) | (spread6(cz) << 2));
}

// ---------------- grid build ----------------
__global__ void __launch_bounds__(1024) zero_kernel() {
    int i = blockIdx.x * 1024 + threadIdx.x;       // 512*1024 == BB*GD3
    g_cnt[i] = 0;
    if (i < 64) { g_sum[i] = 0.f; g_sumsq[i] = 0.f; }
}

__global__ void __launch_bounds__(256) count_kernel(const float* __restrict__ xyz) {
    int t = blockIdx.x * 256 + threadIdx.x;        // 64*256 == NPTS
    int b = t >> 13, i = t & (NN-1);
    const float* p = xyz + ((size_t)b*NN + i)*3;
    int c = mortonOf(cellCoord(p[0]), cellCoord(p[1]), cellCoord(p[2]));
    atomicAdd(&g_cnt[b*GD3 + c], 1);
}

__global__ void __launch_bounds__(1024) scan_kernel() {
    __shared__ int ssum[1024];
    int b = blockIdx.x, tid = threadIdx.x;
    const int* cnt = g_cnt + b*GD3;
    int* start = g_start + b*(GD3+1);
    int base = tid * CPT;
    int s = 0;
    for (int k = 0; k < CPT; k++) s += cnt[base + k];
    ssum[tid] = s;
    __syncthreads();
    for (int d = 1; d < 1024; d <<= 1) {
        int v = (tid >= d) ? ssum[tid - d] : 0;
        __syncthreads();
        ssum[tid] += v;
        __syncthreads();
    }
    int run = (tid == 0) ? 0 : ssum[tid - 1];
    for (int k = 0; k < CPT; k++) {
        start[base + k] = run;
        g_cur[b*GD3 + base + k] = run;
        run += cnt[base + k];
    }
    if (tid == 1023) start[GD3] = run;
}

__global__ void __launch_bounds__(256) scatter_kernel(const float* __restrict__ xyz) {
    int t = blockIdx.x * 256 + threadIdx.x;
    int b = t >> 13, i = t & (NN-1);
    const float* p = xyz + ((size_t)b*NN + i)*3;
    float x = p[0], y = p[1], z = p[2];
    int c = mortonOf(cellCoord(x), cellCoord(y), cellCoord(z));
    int pos = atomicAdd(&g_cur[b*GD3 + c], 1);
    g_pts[b*NN + pos] = make_float4(x, y, z, fmaf(z, z, fmaf(y, y, x*x)));
    g_sid[b*NN + pos] = i;
}

// ---------------- KNN ----------------
__device__ __forceinline__ void insert16(float d, int idx, float* d16, int* i16, float& worst) {
    bool done = false;
    #pragma unroll
    for (int s = 0; s < KNBR; s++)
        if (!done && d16[s] == worst) { d16[s] = d; i16[s] = idx; done = true; }
    worst = d16[0];
    #pragma unroll
    for (int s = 1; s < KNBR; s++) worst = fmaxf(worst, d16[s]);
}

// min distance from q to outside of cell-box [xl..xh]x[yl..yh]x[zl..zh]; clamped faces -> INF
__device__ __forceinline__ float boxMinDist(float4 q, int xl, int xh, int yl, int yh, int zl, int zh) {
    float m = 1e30f;
    if (xl > 0)     m = fminf(m, q.x - (XMIN + (float)xl*HCELL));
    if (xh < GD-1)  m = fminf(m, (XMIN + (float)(xh+1)*HCELL) - q.x);
    if (yl > 0)     m = fminf(m, q.y - (XMIN + (float)yl*HCELL));
    if (yh < GD-1)  m = fminf(m, (XMIN + (float)(yh+1)*HCELL) - q.y);
    if (zl > 0)     m = fminf(m, q.z - (XMIN + (float)zl*HCELL));
    if (zh < GD-1)  m = fminf(m, (XMIN + (float)(zh+1)*HCELL) - q.z);
    return m;
}

__global__ void __launch_bounds__(64) knn_search_kernel() {
    __shared__ unsigned sM[64];
    int tid = threadIdx.x;
    if (tid < 64) sM[tid] = spread6(tid);
    __syncthreads();

    int t = blockIdx.x * 64 + tid;           // query = Morton-sorted point index
    int lane = tid & 31;
    int b = t >> 13;                         // 32 | 8192: warps never straddle batches
    float4 q = g_pts[t];
    int cx = cellCoord(q.x), cy = cellCoord(q.y), cz = cellCoord(q.z);
    const int* start = g_start + b*(GD3+1);
    const float4* pts = g_pts + (size_t)b*NN;

    // warp bbox of query cells (tight thanks to Morton order)
    int bxl = cx, bxh = cx, byl = cy, byh = cy, bzl = cz, bzh = cz;
    #pragma unroll
    for (int o = 16; o; o >>= 1) {
        bxl = min(bxl, __shfl_xor_sync(0xffffffffu, bxl, o));
        bxh = max(bxh, __shfl_xor_sync(0xffffffffu, bxh, o));
        byl = min(byl, __shfl_xor_sync(0xffffffffu, byl, o));
        byh = max(byh, __shfl_xor_sync(0xffffffffu, byh, o));
        bzl = min(bzl, __shfl_xor_sync(0xffffffffu, bzl, o));
        bzh = max(bzh, __shfl_xor_sync(0xffffffffu, bzh, o));
    }

    float d16[KNBR]; int i16[KNBR];
    #pragma unroll
    for (int i = 0; i < KNBR; i++) { d16[i] = 3.4e38f; i16[i] = 0; }
    float worst = 3.4e38f;

    int vol = (bxh-bxl+3) * (byh-byl+3) * (bzh-bzl+3);
    if (vol <= 1728) {
        // ---- main path: warp-shared stream, incremental shells around bbox ----
        for (int S = 1; S <= GD; S++) {
            int zlo = max(bzl-S,0), zhi = min(bzh+S,GD-1);
            int ylo = max(byl-S,0), yhi = min(byh+S,GD-1);
            int xlo = max(bxl-S,0), xhi = min(bxh+S,GD-1);
            for (int zz = zlo; zz <= zhi; zz++) {
                int dz = max(max(bzl-zz, zz-bzh), 0);
                for (int yy = ylo; yy <= yhi; yy++) {
                    int dy = max(max(byl-yy, yy-byh), 0);
                    int dzy = max(dz, dy);
                    for (int xx = xlo; xx <= xhi; xx++) {
                        int cheb = max(dzy, max(max(bxl-xx, xx-bxh), 0));
                        bool take = (S == 1) ? (cheb <= 1) : (cheb == S);
                        if (!take) continue;
                        int mc = (int)(sM[xx] | (sM[yy] << 1) | (sM[zz] << 2));
                        int j0 = start[mc], j1 = start[mc+1];
                        for (int jb = j0; jb < j1; jb += 32) {
                            int rlen = min(32, j1 - jb);
                            float4 p = make_float4(0.f, 0.f, 0.f, 1e30f);
                            if (lane < rlen) p = pts[jb + lane];
                            for (int r = 0; r < rlen; r++) {
                                float px = __shfl_sync(0xffffffffu, p.x, r);
                                float py = __shfl_sync(0xffffffffu, p.y, r);
                                float pz = __shfl_sync(0xffffffffu, p.z, r);
                                float pw = __shfl_sync(0xffffffffu, p.w, r);
                                float dot = fmaf(q.z, pz, fmaf(q.y, py, q.x*px));
                                float d = q.w + pw - 2.0f * dot;   // same form as reference
                                if (d < worst) insert16(d, jb + r, d16, i16, worst);
                            }
                        }
                    }
                }
            }
            float mind = boxMinDist(q, max(bxl-S,0), min(bxh+S,GD-1),
                                       max(byl-S,0), min(byh+S,GD-1),
                                       max(bzl-S,0), min(bzh+S,GD-1));
            bool mydone = (worst <= mind*mind - 1e-3f);
            if (__all_sync(0xffffffffu, mydone)) break;
        }
    } else {
        // ---- fallback (rare Morton-jump warps): lane-private incremental shells ----
        bool done = false;
        for (int S = 1; S <= GD && !done; S++) {
            int zlo = max(cz-S,0), zhi = min(cz+S,GD-1);
            int ylo = max(cy-S,0), yhi = min(cy+S,GD-1);
            int xlo = max(cx-S,0), xhi = min(cx+S,GD-1);
            for (int zz = zlo; zz <= zhi; zz++) {
                int dz = abs(zz - cz);
                for (int yy = ylo; yy <= yhi; yy++) {
                    int dzy = max(dz, abs(yy - cy));
                    for (int xx = xlo; xx <= xhi; xx++) {
                        int cheb = max(dzy, abs(xx - cx));
                        bool take = (S == 1) ? (cheb <= 1) : (cheb == S);
                        if (!take) continue;
                        int mc = (int)(sM[xx] | (sM[yy] << 1) | (sM[zz] << 2));
                        int j0 = start[mc], j1 = start[mc+1];
                        for (int j = j0; j < j1; j++) {
                            float4 p = pts[j];
                            float dot = fmaf(q.z, p.z, fmaf(q.y, p.y, q.x*p.x));
                            float d = q.w + p.w - 2.0f * dot;
                            if (d < worst) insert16(d, j, d16, i16, worst);
                        }
                    }
                }
            }
            float mind = boxMinDist(q, xlo, xhi, ylo, yhi, zlo, zhi);
            done = (worst <= mind*mind - 1e-3f);
        }
    }

    // ---- per-lane exact selection sort + write ----
    int outIdx[KNBR];
    #pragma unroll
    for (int m = 0; m < KNBR; m++) {
        float lm = d16[0]; int lp = 0;
        #pragma unroll
        for (int i = 1; i < KNBR; i++) if (d16[i] < lm) { lm = d16[i]; lp = i; }
        outIdx[m] = i16[lp];
        d16[lp] = 3.4e38f;
    }
    int qi = g_sid[t];
    size_t ob = ((size_t)(b*NN + qi)) * KNBR;
    #pragma unroll
    for (int m = 0; m < KNBR; m++) g_knn[ob + m] = g_sid[(size_t)b*NN + outIdx[m]];
}

// ---------------- K1: projections q,k,v = feats @ W ----------------
#define PROJ_SMEM ((64*132 + 64*64)*4)
__global__ void __launch_bounds__(256) proj_kernel(
    const float* __restrict__ feats,
    const float* __restrict__ wq, const float* __restrict__ wk, const float* __restrict__ wv)
{
    extern __shared__ float sm[];
    float* sFt = sm;            // [64][132] feats^T (k-major)
    float* sW  = sm + 64*132;   // [64][64]
    int tid = threadIdx.x;
    int R0 = blockIdx.x * 128;
    for (int i = tid; i < 128*16; i += 256) {
        int r = i >> 4, c4 = (i & 15) << 2;
        float4 v = *(const float4*)(feats + (size_t)(R0 + r)*64 + c4);
        sFt[(c4+0)*132 + r] = v.x;
        sFt[(c4+1)*132 + r] = v.y;
        sFt[(c4+2)*132 + r] = v.z;
        sFt[(c4+3)*132 + r] = v.w;
    }
    int tm = tid >> 5, tn = tid & 31, c0 = tn * 2;
    int mbase = tm << 4;
    const float* Ws[3] = {wq, wk, wv};
    float* Os[3] = {g_q, g_kf, g_vf};
    for (int mat = 0; mat < 3; mat++) {
        __syncthreads();
        for (int i = tid; i < 1024; i += 256)
            *(float4*)(sW + i*4) = *(const float4*)(Ws[mat] + i*4);
        __syncthreads();
        unsigned long long a0[8], a1[8];
        #pragma unroll
        for (int p = 0; p < 8; p++) { a0[p] = 0ull; a1[p] = 0ull; }
        gemm_f32x2(sFt, sW, mbase, c0, a0, a1);
        float* O = Os[mat];
        #pragma unroll
        for (int p = 0; p < 8; p++) {
            float2 r0 = up2(a0[p]);
            float2 r1 = up2(a1[p]);
            *(float2*)(O + (size_t)(R0 + mbase + 2*p)*64 + c0)   = make_float2(r0.x, r1.x);
            *(float2*)(O + (size_t)(R0 + mbase + 2*p+1)*64 + c0) = make_float2(r0.y, r1.y);
        }
    }
}

// ---------------- K3: mega fused kernel ----------------
#define FUSED_SMEM ((64*132 + 3*64*64 + 192 + 256 + 128)*4)
__global__ void __launch_bounds__(256, 2) fused_kernel(
    const float* __restrict__ xyz, const float* __restrict__ feats,
    const float* __restrict__ w1d, const float* __restrict__ b1d,
    const float* __restrict__ w2d, const float* __restrict__ b2d,
    const float* __restrict__ w1g, const float* __restrict__ b1g,
    const float* __restrict__ w2g, const float* __restrict__ b2g)
{
    extern __shared__ float sm[];
    float* sA   = sm;                 // [64][132]
    float* sW2d = sA   + 64*132;      // [64][64]
    float* sW1g = sW2d + 4096;
    float* sW2g = sW1g + 4096;
    float* sW1d = sW2g + 4096;        // [3][64]
    float* sB   = sW1d + 192;         // b1d|b2d|b1g|b2g
    int*   sIdx = (int*)(sB + 256);   // [128]
    int tid = threadIdx.x;

    for (int i = tid; i < 1024; i += 256) {
        *(float4*)(sW2d + i*4) = *(const float4*)(w2d + i*4);
        *(float4*)(sW1g + i*4) = *(const float4*)(w1g + i*4);
        *(float4*)(sW2g + i*4) = *(const float4*)(w2g + i*4);
    }
    if (tid < 192) sW1d[tid] = w1d[tid];
    if (tid < 64) { sB[tid] = b1d[tid]; sB[64+tid] = b2d[tid]; sB[128+tid] = b1g[tid]; sB[192+tid] = b2g[tid]; }

    int R0 = blockIdx.x * 128;
    int P0 = blockIdx.x * 8;
    int b  = P0 >> 13;
    __syncthreads();

    // ---- stage H1 = relu(dxyz @ W1d + b1d) into sA (k-major) ----
    {
        int m   = tid >> 1;
        int row = R0 + m;
        int pn  = row >> 4;
        int nl  = pn & (NN - 1);
        int j   = g_knn[row];
        if ((tid & 1) == 0) sIdx[m] = j;
        const float* xb = xyz + (size_t)b * NN * 3;
        float dx = xb[nl*3+0] - xb[j*3+0];
        float dy = xb[nl*3+1] - xb[j*3+1];
        float dz = xb[nl*3+2] - xb[j*3+2];
        int cb = (tid & 1) * 32;
        #pragma unroll 8
        for (int c = 0; c < 32; c++) {
            int cc = cb + c;
            float h = fmaf(dz, sW1d[128+cc], fmaf(dy, sW1d[64+cc], fmaf(dx, sW1d[cc], sB[cc])));
            sA[cc*132 + m] = fmaxf(h, 0.f);
        }
    }
    __syncthreads();

    int tm = tid >> 5, tn = tid & 31, c0 = tn * 2;
    int mbase = tm << 4;
    int pn0 = P0 + tm;

    // ---- GEMM1: pos = H1 @ W2d + b2d ----
    unsigned long long a0[8], a1[8];
    {
        unsigned long long bb0 = pk2(sB[64+c0],   sB[64+c0]);
        unsigned long long bb1 = pk2(sB[64+c0+1], sB[64+c0+1]);
        #pragma unroll
        for (int p = 0; p < 8; p++) { a0[p] = bb0; a1[p] = bb1; }
        gemm_f32x2(sA, sW2d, mbase, c0, a0, a1);
    }
    __syncthreads();

    // ---- epilogue: x = q - kf + pos -> sA ; val = vf + pos -> v0/v1 ----
    float v0[KNBR], v1[KNBR];
    {
        float2 qv = *(const float2*)(g_q + (size_t)pn0*64 + c0);
        #pragma unroll
        for (int p = 0; p < 8; p++) {
            float2 ps0 = up2(a0[p]);
            float2 ps1 = up2(a1[p]);
            int j0 = sIdx[mbase + 2*p];
            int j1 = sIdx[mbase + 2*p + 1];
            size_t gp0 = ((size_t)(b*NN + j0))*64 + c0;
            size_t gp1 = ((size_t)(b*NN + j1))*64 + c0;
            float2 kf0 = *(const float2*)(g_kf + gp0);
            float2 kf1 = *(const float2*)(g_kf + gp1);
            float2 vf0 = *(const float2*)(g_vf + gp0);
            float2 vf1 = *(const float2*)(g_vf + gp1);
            v0[2*p]   = vf0.x + ps0.x;  v1[2*p]   = vf0.y + ps1.x;
            v0[2*p+1] = vf1.x + ps0.y;  v1[2*p+1] = vf1.y + ps1.y;
            *(float2*)(sA + c0*132     + mbase + 2*p) = make_float2(qv.x - kf0.x + ps0.x, qv.x - kf1.x + ps0.y);
            *(float2*)(sA + (c0+1)*132 + mbase + 2*p) = make_float2(qv.y - kf0.y + ps1.x, qv.y - kf1.y + ps1.y);
        }
    }
    __syncthreads();

    // ---- GEMM2: g1 = relu(x @ W1g + b1g) ----
    {
        unsigned long long bb0 = pk2(sB[128+c0],   sB[128+c0]);
        unsigned long long bb1 = pk2(sB[128+c0+1], sB[128+c0+1]);
        #pragma unroll
        for (int p = 0; p < 8; p++) { a0[p] = bb0; a1[p] = bb1; }
        gemm_f32x2(sA, sW1g, mbase, c0, a0, a1);
    }
    __syncthreads();
    #pragma unroll
    for (int p = 0; p < 8; p++) {
        float2 r0 = up2(a0[p]), r1 = up2(a1[p]);
        *(float2*)(sA + c0*132     + mbase + 2*p) = make_float2(fmaxf(r0.x,0.f), fmaxf(r0.y,0.f));
        *(float2*)(sA + (c0+1)*132 + mbase + 2*p) = make_float2(fmaxf(r1.x,0.f), fmaxf(r1.y,0.f));
    }
    __syncthreads();

    // ---- GEMM3: logits = g1 @ W2g + b2g ----
    {
        unsigned long long bb0 = pk2(sB[192+c0],   sB[192+c0]);
        unsigned long long bb1 = pk2(sB[192+c0+1], sB[192+c0+1]);
        #pragma unroll
        for (int p = 0; p < 8; p++) { a0[p] = bb0; a1[p] = bb1; }
        gemm_f32x2(sA, sW2g, mbase, c0, a0, a1);
    }

    // ---- softmax over K (thread-local) + weighted sum + residual ----
    float t0a[KNBR], t1a[KNBR];
    #pragma unroll
    for (int p = 0; p < 8; p++) {
        float2 r0 = up2(a0[p]), r1 = up2(a1[p]);
        t0a[2*p] = r0.x; t0a[2*p+1] = r0.y;
        t1a[2*p] = r1.x; t1a[2*p+1] = r1.y;
    }
    float m0 = t0a[0], m1 = t1a[0];
    #pragma unroll
    for (int s = 1; s < KNBR; s++) { m0 = fmaxf(m0, t0a[s]); m1 = fmaxf(m1, t1a[s]); }
    float s0 = 0.f, s1 = 0.f;
    #pragma unroll
    for (int s = 0; s < KNBR; s++) {
        t0a[s] = __expf(t0a[s] - m0);  s0 += t0a[s];
        t1a[s] = __expf(t1a[s] - m1);  s1 += t1a[s];
    }
    float r0 = 0.f, r1 = 0.f;
    #pragma unroll
    for (int s = 0; s < KNBR; s++) { r0 = fmaf(t0a[s], v0[s], r0); r1 = fmaf(t1a[s], v1[s], r1); }
    float2 fv = *(const float2*)(feats + (size_t)pn0*64 + c0);
    r0 = r0 / s0 + fv.x;
    r1 = r1 / s1 + fv.y;
    *(float2*)(g_res + (size_t)pn0*64 + c0) = make_float2(r0, r1);

    // ---- BN partial sums ----
    __syncthreads();
    if (tid < 128) sA[tid] = 0.f;
    __syncthreads();
    atomicAdd(&sA[c0],      r0);
    atomicAdd(&sA[c0+1],    r1);
    atomicAdd(&sA[64+c0],   r0*r0);
    atomicAdd(&sA[64+c0+1], r1*r1);
    __syncthreads();
    if (tid < 64) {
        atomicAdd(&g_sum[tid],   sA[tid]);
        atomicAdd(&g_sumsq[tid], sA[64+tid]);
    }
}

// ---------------- K4: BatchNorm apply ----------------
__global__ void __launch_bounds__(256) bn_kernel(
    const float* __restrict__ bn_gamma, const float* __restrict__ bn_beta,
    float* __restrict__ out)
{
    int idx = blockIdx.x * 256 + threadIdx.x;
    int c = idx & 63;
    float inv = 1.0f / (float)NPTS;
    float mean = g_sum[c] * inv;
    float var  = g_sumsq[c] * inv - mean * mean;
    out[idx] = (g_res[idx] - mean) * rsqrtf(var + 1e-5f) * bn_gamma[c] + bn_beta[c];
}

// ---------------- launch ----------------
extern "C" void kernel_launch(void* const* d_in, const int* in_sizes, int n_in,
                              void* d_out, int out_size)
{
    const float* xyz   = (const float*)d_in[0];
    const float* feats = (const float*)d_in[1];
    const float* wq    = (const float*)d_in[2];
    const float* wk    = (const float*)d_in[3];
    const float* wv    = (const float*)d_in[4];
    const float* dw1   = (const float*)d_in[5];
    const float* db1   = (const float*)d_in[6];
    const float* dw2   = (const float*)d_in[7];
    const float* db2   = (const float*)d_in[8];
    const float* gw1   = (const float*)d_in[9];
    const float* gb1   = (const float*)d_in[10];
    const float* gw2   = (const float*)d_in[11];
    const float* gb2   = (const float*)d_in[12];
    const float* bng   = (const float*)d_in[13];
    const float* bnb   = (const float*)d_in[14];
    float* out = (float*)d_out;

    cudaFuncSetAttribute(proj_kernel,  cudaFuncAttributeMaxDynamicSharedMemorySize, PROJ_SMEM);
    cudaFuncSetAttribute(fused_kernel, cudaFuncAttributeMaxDynamicSharedMemorySize, FUSED_SMEM);

    zero_kernel      <<<(BB*GD3)/1024, 1024>>>();
    count_kernel     <<<NPTS/256, 256>>>(xyz);
    scan_kernel      <<<BB, 1024>>>();
    scatter_kernel   <<<NPTS/256, 256>>>(xyz);
    knn_search_kernel<<<NPTS/64, 64>>>();     // 2 warps/block; warp = 32 Morton-adjacent queries
    proj_kernel      <<<128, 256, PROJ_SMEM>>>(feats, wq, wk, wv);
    fused_kernel     <<<2048, 256, FUSED_SMEM>>>(xyz, feats, dw1, db1, dw2, db2, gw1, gb1, gw2, gb2);
    bn_kernel        <<<4096, 256>>>(bng, bnb, out);
}

// round 10
// speedup vs baseline: 1.9705x; 1.9705x over previous
#include <cuda_runtime.h>
#include <math.h>

#define BB 2
#define NN 8192
#define DD 64
#define KNBR 16
#define NPTS (BB*NN)          // 16384
#define ROWS (NPTS*KNBR)      // 262144

// ---- 1-D x-bucket sort for KNN ----
#define NB   8192
#define XLO  (-9.0f)
#define XRNG 18.0f
#define BW   (XRNG/NB)        // 0.0021973
#define INVBW ((float)NB/XRNG)

// ---------------- scratch (static device arrays; no allocation) ----------------
__device__ float  g_q  [NPTS*DD];
__device__ float  g_kf [NPTS*DD];
__device__ float  g_vf [NPTS*DD];
__device__ int    g_knn[ROWS];
__device__ float  g_res[NPTS*DD];
__device__ float  g_sum[DD];
__device__ float  g_sumsq[DD];
__device__ int    g_cnt  [BB*NB];
__device__ int    g_cur  [BB*NB];
__device__ float4 g_pts  [NPTS];     // x-bucket-sorted (x,y,z,|p|^2) per batch
__device__ int    g_sid  [NPTS];     // original index of sorted point

// ---------------- packed f32x2 helpers ----------------
__device__ __forceinline__ void fma2(unsigned long long &d, unsigned long long a, unsigned long long b) {
    asm("fma.rn.f32x2 %0, %1, %2, %0;" : "+l"(d) : "l"(a), "l"(b));
}
__device__ __forceinline__ unsigned long long pk2(float lo, float hi) {
    unsigned long long r; asm("mov.b64 %0, {%1,%2};" : "=l"(r) : "f"(lo), "f"(hi)); return r;
}
__device__ __forceinline__ float2 up2(unsigned long long v) {
    float2 r; asm("mov.b64 {%0,%1}, %2;" : "=f"(r.x), "=f"(r.y) : "l"(v)); return r;
}

// 128x64 GEMM slice. sA: k-major [64][132]; sW: row-major [64][64].
__device__ __forceinline__ void gemm_f32x2(const float* __restrict__ sA, const float* __restrict__ sW,
                                           int mbase, int c0,
                                           unsigned long long* a0, unsigned long long* a1)
{
    #pragma unroll 4
    for (int kk = 0; kk < 64; kk++) {
        const ulonglong2* ap = (const ulonglong2*)(sA + kk*132 + mbase);   // broadcast LDS.128
        float2 w = *(const float2*)(sW + kk*64 + c0);                      // LDS.64
        unsigned long long w0 = pk2(w.x, w.x);
        unsigned long long w1 = pk2(w.y, w.y);
        ulonglong2 A0 = ap[0], A1 = ap[1];
        fma2(a0[0], A0.x, w0); fma2(a1[0], A0.x, w1);
        fma2(a0[1], A0.y, w0); fma2(a1[1], A0.y, w1);
        fma2(a0[2], A1.x, w0); fma2(a1[2], A1.x, w1);
        fma2(a0[3], A1.y, w0); fma2(a1[3], A1.y, w1);
        ulonglong2 A2 = ap[2], A3 = ap[3];
        fma2(a0[4], A2.x, w0); fma2(a1[4], A2.x, w1);
        fma2(a0[5], A2.y, w0); fma2(a1[5], A2.y, w1);
        fma2(a0[6], A3.x, w0); fma2(a1[6], A3.x, w1);
        fma2(a0[7], A3.y, w0); fma2(a1[7], A3.y, w1);
    }
}

// ---------------- bucket sort build ----------------
__device__ __forceinline__ int bucketOf(float x) {
    int c = (int)((x - XLO) * INVBW);
    return min(max(c, 0), NB-1);
}

__global__ void __launch_bounds__(1024) zero_kernel() {
    int i = blockIdx.x * 1024 + threadIdx.x;       // 16*1024 == BB*NB
    g_cnt[i] = 0;
    if (i < 64) { g_sum[i] = 0.f; g_sumsq[i] = 0.f; }
}

__global__ void __launch_bounds__(256) count_kernel(const float* __restrict__ xyz) {
    int t = blockIdx.x * 256 + threadIdx.x;        // 64*256 == NPTS
    int b = t >> 13, i = t & (NN-1);
    atomicAdd(&g_cnt[b*NB + bucketOf(xyz[((size_t)b*NN + i)*3])], 1);
}

// exclusive prefix over NB buckets, one block per batch
__global__ void __launch_bounds__(1024) scan_kernel() {
    __shared__ int ssum[1024];
    int b = blockIdx.x, tid = threadIdx.x;
    const int* cnt = g_cnt + b*NB;
    int base = tid * 8;                            // 1024*8 == NB
    int s = 0;
    #pragma unroll
    for (int k = 0; k < 8; k++) s += cnt[base + k];
    ssum[tid] = s;
    __syncthreads();
    for (int d = 1; d < 1024; d <<= 1) {
        int v = (tid >= d) ? ssum[tid - d] : 0;
        __syncthreads();
        ssum[tid] += v;
        __syncthreads();
    }
    int run = (tid == 0) ? 0 : ssum[tid - 1];
    #pragma unroll
    for (int k = 0; k < 8; k++) {
        g_cur[b*NB + base + k] = run;
        run += cnt[base + k];
    }
}

__global__ void __launch_bounds__(256) scatter_kernel(const float* __restrict__ xyz) {
    int t = blockIdx.x * 256 + threadIdx.x;
    int b = t >> 13, i = t & (NN-1);
    const float* p = xyz + ((size_t)b*NN + i)*3;
    float x = p[0], y = p[1], z = p[2];
    int pos = atomicAdd(&g_cur[b*NB + bucketOf(x)], 1);
    g_pts[b*NN + pos] = make_float4(x, y, z, fmaf(z, z, fmaf(y, y, x*x)));
    g_sid[b*NN + pos] = i;
}

// ---------------- KNN: warp-windowed scan over x-sorted stream (exact) ----------------
__device__ __forceinline__ void insert16(float d, int idx, float* d16, int* i16, float& worst) {
    bool done = false;
    #pragma unroll
    for (int s = 0; s < KNBR; s++)
        if (!done && d16[s] == worst) { d16[s] = d; i16[s] = idx; done = true; }
    worst = d16[0];
    #pragma unroll
    for (int s = 1; s < KNBR; s++) worst = fmaxf(worst, d16[s]);
}

__global__ void __launch_bounds__(64) knn_search_kernel() {
    int t = blockIdx.x * 64 + threadIdx.x;   // global sorted query index
    int b = t >> 13;                         // 32 | 8192 -> warps never straddle batches
    int tq = t & (NN-1);                     // local sorted index
    const float4* __restrict__ pts = g_pts + (size_t)b*NN;
    float4 q = pts[tq];

    float d16[KNBR]; int i16[KNBR];
    #pragma unroll
    for (int i = 0; i < KNBR; i++) { d16[i] = 3.4e38f; i16[i] = 0; }
    float worst = 3.4e38f;

    int t0 = tq & ~31;                       // warp window seed
    int L = t0, R = t0 + 32;

    // scan own block first (includes self: d == 0 exactly)
    #pragma unroll 4
    for (int j = t0; j < t0 + 32; j++) {
        float4 p = pts[j];
        float dot = fmaf(q.z, p.z, fmaf(q.y, p.y, q.x*p.x));
        float d = q.w + p.w - 2.0f * dot;    // same expansion form as reference
        if (d < worst) insert16(d, j, d16, i16, worst);
    }

    // expand window until every lane's top-16 is provably final
    for (;;) {
        bool doneR, doneL;
        if (R < NN) {
            float gap = pts[R].x - BW - q.x;           // uniform (broadcast) load
            doneR = (gap > 0.f) && (gap*gap >= worst);
        } else doneR = true;
        if (L > 0) {
            float gap = q.x - (pts[L-1].x + BW);       // uniform load
            doneL = (gap > 0.f) && (gap*gap >= worst);
        } else doneL = true;

        bool scanR = !__all_sync(0xffffffffu, doneR);
        bool scanL = !__all_sync(0xffffffffu, doneL);
        if (!scanR && !scanL) break;

        if (scanR) {
            int j1 = min(R + 32, NN);
            #pragma unroll 4
            for (int j = R; j < j1; j++) {
                float4 p = pts[j];
                float dot = fmaf(q.z, p.z, fmaf(q.y, p.y, q.x*p.x));
                float d = q.w + p.w - 2.0f * dot;
                if (d < worst) insert16(d, j, d16, i16, worst);
            }
            R = j1;
        }
        if (scanL) {
            int j0 = max(L - 32, 0);
            #pragma unroll 4
            for (int j = j0; j < L; j++) {
                float4 p = pts[j];
                float dot = fmaf(q.z, p.z, fmaf(q.y, p.y, q.x*p.x));
                float d = q.w + p.w - 2.0f * dot;
                if (d < worst) insert16(d, j, d16, i16, worst);
            }
            L = j0;
        }
    }

    // per-lane exact selection sort + map to original ids + write
    int outIdx[KNBR];
    #pragma unroll
    for (int m = 0; m < KNBR; m++) {
        float lm = d16[0]; int lp = 0;
        #pragma unroll
        for (int i = 1; i < KNBR; i++) if (d16[i] < lm) { lm = d16[i]; lp = i; }
        outIdx[m] = i16[lp];
        d16[lp] = 3.4e38f;
    }
    int qi = g_sid[(size_t)b*NN + tq];
    size_t ob = ((size_t)(b*NN + qi)) * KNBR;
    #pragma unroll
    for (int m = 0; m < KNBR; m++) g_knn[ob + m] = g_sid[(size_t)b*NN + outIdx[m]];
}

// ---------------- K1: projections q,k,v = feats @ W ----------------
#define PROJ_SMEM ((64*132 + 64*64)*4)
__global__ void __launch_bounds__(256) proj_kernel(
    const float* __restrict__ feats,
    const float* __restrict__ wq, const float* __restrict__ wk, const float* __restrict__ wv)
{
    extern __shared__ float sm[];
    float* sFt = sm;            // [64][132] feats^T (k-major)
    float* sW  = sm + 64*132;   // [64][64]
    int tid = threadIdx.x;
    int R0 = blockIdx.x * 128;
    for (int i = tid; i < 128*16; i += 256) {
        int r = i >> 4, c4 = (i & 15) << 2;
        float4 v = *(const float4*)(feats + (size_t)(R0 + r)*64 + c4);
        sFt[(c4+0)*132 + r] = v.x;
        sFt[(c4+1)*132 + r] = v.y;
        sFt[(c4+2)*132 + r] = v.z;
        sFt[(c4+3)*132 + r] = v.w;
    }
    int tm = tid >> 5, tn = tid & 31, c0 = tn * 2;
    int mbase = tm << 4;
    const float* Ws[3] = {wq, wk, wv};
    float* Os[3] = {g_q, g_kf, g_vf};
    for (int mat = 0; mat < 3; mat++) {
        __syncthreads();
        for (int i = tid; i < 1024; i += 256)
            *(float4*)(sW + i*4) = *(const float4*)(Ws[mat] + i*4);
        __syncthreads();
        unsigned long long a0[8], a1[8];
        #pragma unroll
        for (int p = 0; p < 8; p++) { a0[p] = 0ull; a1[p] = 0ull; }
        gemm_f32x2(sFt, sW, mbase, c0, a0, a1);
        float* O = Os[mat];
        #pragma unroll
        for (int p = 0; p < 8; p++) {
            float2 r0 = up2(a0[p]);
            float2 r1 = up2(a1[p]);
            *(float2*)(O + (size_t)(R0 + mbase + 2*p)*64 + c0)   = make_float2(r0.x, r1.x);
            *(float2*)(O + (size_t)(R0 + mbase + 2*p+1)*64 + c0) = make_float2(r0.y, r1.y);
        }
    }
}

// ---------------- K3: mega fused kernel (single reusable weight buffer) ----------------
#define FUSED_SMEM ((64*132 + 64*64 + 192 + 256 + 128)*4)
__global__ void __launch_bounds__(256, 2) fused_kernel(
    const float* __restrict__ xyz, const float* __restrict__ feats,
    const float* __restrict__ w1d, const float* __restrict__ b1d,
    const float* __restrict__ w2d, const float* __restrict__ b2d,
    const float* __restrict__ w1g, const float* __restrict__ b1g,
    const float* __restrict__ w2g, const float* __restrict__ b2g)
{
    extern __shared__ float sm[];
    float* sA   = sm;                 // [64][132]
    float* sW   = sA + 64*132;        // [64][64] (reused for W2d, W1g, W2g)
    float* sW1d = sW + 4096;          // [3][64]
    float* sB   = sW1d + 192;         // b1d|b2d|b1g|b2g
    int*   sIdx = (int*)(sB + 256);   // [128]
    int tid = threadIdx.x;

    for (int i = tid; i < 1024; i += 256)
        *(float4*)(sW + i*4) = *(const float4*)(w2d + i*4);
    if (tid < 192) sW1d[tid] = w1d[tid];
    if (tid < 64) { sB[tid] = b1d[tid]; sB[64+tid] = b2d[tid]; sB[128+tid] = b1g[tid]; sB[192+tid] = b2g[tid]; }

    int R0 = blockIdx.x * 128;
    int P0 = blockIdx.x * 8;
    int b  = P0 >> 13;
    __syncthreads();

    // ---- stage H1 = relu(dxyz @ W1d + b1d) into sA (k-major) ----
    {
        int m   = tid >> 1;
        int row = R0 + m;
        int pn  = row >> 4;
        int nl  = pn & (NN - 1);
        int j   = g_knn[row];
        if ((tid & 1) == 0) sIdx[m] = j;
        const float* xb = xyz + (size_t)b * NN * 3;
        float dx = xb[nl*3+0] - xb[j*3+0];
        float dy = xb[nl*3+1] - xb[j*3+1];
        float dz = xb[nl*3+2] - xb[j*3+2];
        int cb = (tid & 1) * 32;
        #pragma unroll 8
        for (int c = 0; c < 32; c++) {
            int cc = cb + c;
            float h = fmaf(dz, sW1d[128+cc], fmaf(dy, sW1d[64+cc], fmaf(dx, sW1d[cc], sB[cc])));
            sA[cc*132 + m] = fmaxf(h, 0.f);
        }
    }
    __syncthreads();

    int tm = tid >> 5, tn = tid & 31, c0 = tn * 2;
    int mbase = tm << 4;
    int pn0 = P0 + tm;

    // ---- GEMM1: pos = H1 @ W2d + b2d ----
    unsigned long long a0[8], a1[8];
    {
        unsigned long long bb0 = pk2(sB[64+c0],   sB[64+c0]);
        unsigned long long bb1 = pk2(sB[64+c0+1], sB[64+c0+1]);
        #pragma unroll
        for (int p = 0; p < 8; p++) { a0[p] = bb0; a1[p] = bb1; }
        gemm_f32x2(sA, sW, mbase, c0, a0, a1);
    }
    __syncthreads();   // done reading H1 (sA) and W2d (sW)

    // ---- epilogue: x = q - kf + pos -> sA ; val = vf + pos -> v0/v1 ; load W1g ----
    float v0[KNBR], v1[KNBR];
    {
        float2 qv = *(const float2*)(g_q + (size_t)pn0*64 + c0);
        #pragma unroll
        for (int p = 0; p < 8; p++) {
            float2 ps0 = up2(a0[p]);
            float2 ps1 = up2(a1[p]);
            int j0 = sIdx[mbase + 2*p];
            int j1 = sIdx[mbase + 2*p + 1];
            size_t gp0 = ((size_t)(b*NN + j0))*64 + c0;
            size_t gp1 = ((size_t)(b*NN + j1))*64 + c0;
            float2 kf0 = *(const float2*)(g_kf + gp0);
            float2 kf1 = *(const float2*)(g_kf + gp1);
            float2 vf0 = *(const float2*)(g_vf + gp0);
            float2 vf1 = *(const float2*)(g_vf + gp1);
            v0[2*p]   = vf0.x + ps0.x;  v1[2*p]   = vf0.y + ps1.x;
            v0[2*p+1] = vf1.x + ps0.y;  v1[2*p+1] = vf1.y + ps1.y;
            *(float2*)(sA + c0*132     + mbase + 2*p) = make_float2(qv.x - kf0.x + ps0.x, qv.x - kf1.x + ps0.y);
            *(float2*)(sA + (c0+1)*132 + mbase + 2*p) = make_float2(qv.y - kf0.y + ps1.x, qv.y - kf1.y + ps1.y);
        }
        for (int i = tid; i < 1024; i += 256)
            *(float4*)(sW + i*4) = *(const float4*)(w1g + i*4);
    }
    __syncthreads();

    // ---- GEMM2: g1 = relu(x @ W1g + b1g) ----
    {
        unsigned long long bb0 = pk2(sB[128+c0],   sB[128+c0]);
        unsigned long long bb1 = pk2(sB[128+c0+1], sB[128+c0+1]);
        #pragma unroll
        for (int p = 0; p < 8; p++) { a0[p] = bb0; a1[p] = bb1; }
        gemm_f32x2(sA, sW, mbase, c0, a0, a1);
    }
    __syncthreads();   // done reading x (sA) and W1g (sW)
    #pragma unroll
    for (int p = 0; p < 8; p++) {
        float2 r0 = up2(a0[p]), r1 = up2(a1[p]);
        *(float2*)(sA + c0*132     + mbase + 2*p) = make_float2(fmaxf(r0.x,0.f), fmaxf(r0.y,0.f));
        *(float2*)(sA + (c0+1)*132 + mbase + 2*p) = make_float2(fmaxf(r1.x,0.f), fmaxf(r1.y,0.f));
    }
    for (int i = tid; i < 1024; i += 256)
        *(float4*)(sW + i*4) = *(const float4*)(w2g + i*4);
    __syncthreads();

    // ---- GEMM3: logits = g1 @ W2g + b2g ----
    {
        unsigned long long bb0 = pk2(sB[192+c0],   sB[192+c0]);
        unsigned long long bb1 = pk2(sB[192+c0+1], sB[192+c0+1]);
        #pragma unroll
        for (int p = 0; p < 8; p++) { a0[p] = bb0; a1[p] = bb1; }
        gemm_f32x2(sA, sW, mbase, c0, a0, a1);
    }

    // ---- softmax over K (thread-local) + weighted sum + residual ----
    float t0a[KNBR], t1a[KNBR];
    #pragma unroll
    for (int p = 0; p < 8; p++) {
        float2 r0 = up2(a0[p]), r1 = up2(a1[p]);
        t0a[2*p] = r0.x; t0a[2*p+1] = r0.y;
        t1a[2*p] = r1.x; t1a[2*p+1] = r1.y;
    }
    float m0 = t0a[0], m1 = t1a[0];
    #pragma unroll
    for (int s = 1; s < KNBR; s++) { m0 = fmaxf(m0, t0a[s]); m1 = fmaxf(m1, t1a[s]); }
    float s0 = 0.f, s1 = 0.f;
    #pragma unroll
    for (int s = 0; s < KNBR; s++) {
        t0a[s] = __expf(t0a[s] - m0);  s0 += t0a[s];
        t1a[s] = __expf(t1a[s] - m1);  s1 += t1a[s];
    }
    float r0 = 0.f, r1 = 0.f;
    #pragma unroll
    for (int s = 0; s < KNBR; s++) { r0 = fmaf(t0a[s], v0[s], r0); r1 = fmaf(t1a[s], v1[s], r1); }
    float2 fv = *(const float2*)(feats + (size_t)pn0*64 + c0);
    r0 = r0 / s0 + fv.x;
    r1 = r1 / s1 + fv.y;
    *(float2*)(g_res + (size_t)pn0*64 + c0) = make_float2(r0, r1);

    // ---- BN partial sums ----
    __syncthreads();
    if (tid < 128) sA[tid] = 0.f;
    __syncthreads();
    atomicAdd(&sA[c0],      r0);
    atomicAdd(&sA[c0+1],    r1);
    atomicAdd(&sA[64+c0],   r0*r0);
    atomicAdd(&sA[64+c0+1], r1*r1);
    __syncthreads();
    if (tid < 64) {
        atomicAdd(&g_sum[tid],   sA[tid]);
        atomicAdd(&g_sumsq[tid], sA[64+tid]);
    }
}

// ---------------- K4: BatchNorm apply ----------------
__global__ void __launch_bounds__(256) bn_kernel(
    const float* __restrict__ bn_gamma, const float* __restrict__ bn_beta,
    float* __restrict__ out)
{
    int idx = blockIdx.x * 256 + threadIdx.x;
    int c = idx & 63;
    float inv = 1.0f / (float)NPTS;
    float mean = g_sum[c] * inv;
    float var  = g_sumsq[c] * inv - mean * mean;
    out[idx] = (g_res[idx] - mean) * rsqrtf(var + 1e-5f) * bn_gamma[c] + bn_beta[c];
}

// ---------------- launch ----------------
extern "C" void kernel_launch(void* const* d_in, const int* in_sizes, int n_in,
                              void* d_out, int out_size)
{
    const float* xyz   = (const float*)d_in[0];
    const float* feats = (const float*)d_in[1];
    const float* wq    = (const float*)d_in[2];
    const float* wk    = (const float*)d_in[3];
    const float* wv    = (const float*)d_in[4];
    const float* dw1   = (const float*)d_in[5];
    const float* db1   = (const float*)d_in[6];
    const float* dw2   = (const float*)d_in[7];
    const float* db2   = (const float*)d_in[8];
    const float* gw1   = (const float*)d_in[9];
    const float* gb1   = (const float*)d_in[10];
    const float* gw2   = (const float*)d_in[11];
    const float* gb2   = (const float*)d_in[12];
    const float* bng   = (const float*)d_in[13];
    const float* bnb   = (const float*)d_in[14];
    float* out = (float*)d_out;

    cudaFuncSetAttribute(proj_kernel,  cudaFuncAttributeMaxDynamicSharedMemorySize, PROJ_SMEM);
    cudaFuncSetAttribute(fused_kernel, cudaFuncAttributeMaxDynamicSharedMemorySize, FUSED_SMEM);

    zero_kernel      <<<(BB*NB)/1024, 1024>>>();
    count_kernel     <<<NPTS/256, 256>>>(xyz);
    scan_kernel      <<<BB, 1024>>>();
    scatter_kernel   <<<NPTS/256, 256>>>(xyz);
    knn_search_kernel<<<NPTS/64, 64>>>();     // warp = 32 x-adjacent queries, windowed scan
    proj_kernel      <<<128, 256, PROJ_SMEM>>>(feats, wq, wk, wv);
    fused_kernel     <<<2048, 256, FUSED_SMEM>>>(xyz, feats, dw1, db1, dw2, db2, gw1, gb1, gw2, gb2);
    bn_kernel        <<<4096, 256>>>(bng, bnb, out);
}

// round 11
// speedup vs baseline: 3.0124x; 1.5287x over previous
#include <cuda_runtime.h>
#include <math.h>

#define BB 2
#define NN 8192
#define DD 64
#define KNBR 16
#define NPTS (BB*NN)          // 16384
#define ROWS (NPTS*KNBR)      // 262144

// ---- 1-D x-bucket sort for KNN ----
#define NB   8192
#define XLO  (-9.0f)
#define XRNG 18.0f
#define BW   (XRNG/NB)        // 0.0021973
#define INVBW ((float)NB/XRNG)

// ---------------- scratch (static device arrays; no allocation) ----------------
__device__ float  g_q  [NPTS*DD];
__device__ float  g_kf [NPTS*DD];
__device__ float  g_vf [NPTS*DD];
__device__ int    g_knn[ROWS];
__device__ float  g_res[NPTS*DD];
__device__ float  g_sum[DD];
__device__ float  g_sumsq[DD];
__device__ int    g_cnt  [BB*NB];
__device__ int    g_cur  [BB*NB];
__device__ float4 g_pts  [NPTS];     // x-bucket-sorted (x,y,z,|p|^2) per batch
__device__ int    g_sid  [NPTS];     // original index of sorted point

// ---------------- packed f32x2 helpers ----------------
__device__ __forceinline__ void fma2(unsigned long long &d, unsigned long long a, unsigned long long b) {
    asm("fma.rn.f32x2 %0, %1, %2, %0;" : "+l"(d) : "l"(a), "l"(b));
}
__device__ __forceinline__ unsigned long long pk2(float lo, float hi) {
    unsigned long long r; asm("mov.b64 %0, {%1,%2};" : "=l"(r) : "f"(lo), "f"(hi)); return r;
}
__device__ __forceinline__ float2 up2(unsigned long long v) {
    float2 r; asm("mov.b64 {%0,%1}, %2;" : "=f"(r.x), "=f"(r.y) : "l"(v)); return r;
}

// 128x64 GEMM slice. sA: k-major [64][132]; sW: row-major [64][64].
__device__ __forceinline__ void gemm_f32x2(const float* __restrict__ sA, const float* __restrict__ sW,
                                           int mbase, int c0,
                                           unsigned long long* a0, unsigned long long* a1)
{
    #pragma unroll 4
    for (int kk = 0; kk < 64; kk++) {
        const ulonglong2* ap = (const ulonglong2*)(sA + kk*132 + mbase);   // broadcast LDS.128
        float2 w = *(const float2*)(sW + kk*64 + c0);                      // LDS.64
        unsigned long long w0 = pk2(w.x, w.x);
        unsigned long long w1 = pk2(w.y, w.y);
        ulonglong2 A0 = ap[0], A1 = ap[1];
        fma2(a0[0], A0.x, w0); fma2(a1[0], A0.x, w1);
        fma2(a0[1], A0.y, w0); fma2(a1[1], A0.y, w1);
        fma2(a0[2], A1.x, w0); fma2(a1[2], A1.x, w1);
        fma2(a0[3], A1.y, w0); fma2(a1[3], A1.y, w1);
        ulonglong2 A2 = ap[2], A3 = ap[3];
        fma2(a0[4], A2.x, w0); fma2(a1[4], A2.x, w1);
        fma2(a0[5], A2.y, w0); fma2(a1[5], A2.y, w1);
        fma2(a0[6], A3.x, w0); fma2(a1[6], A3.x, w1);
        fma2(a0[7], A3.y, w0); fma2(a1[7], A3.y, w1);
    }
}

// ---------------- bucket sort build ----------------
__device__ __forceinline__ int bucketOf(float x) {
    int c = (int)((x - XLO) * INVBW);
    return min(max(c, 0), NB-1);
}

__global__ void __launch_bounds__(1024) zero_kernel() {
    int i = blockIdx.x * 1024 + threadIdx.x;       // 16*1024 == BB*NB
    g_cnt[i] = 0;
    if (i < 64) { g_sum[i] = 0.f; g_sumsq[i] = 0.f; }
}

__global__ void __launch_bounds__(256) count_kernel(const float* __restrict__ xyz) {
    int t = blockIdx.x * 256 + threadIdx.x;        // 64*256 == NPTS
    int b = t >> 13, i = t & (NN-1);
    atomicAdd(&g_cnt[b*NB + bucketOf(xyz[((size_t)b*NN + i)*3])], 1);
}

// exclusive prefix over NB buckets, one block per batch
__global__ void __launch_bounds__(1024) scan_kernel() {
    __shared__ int ssum[1024];
    int b = blockIdx.x, tid = threadIdx.x;
    const int* cnt = g_cnt + b*NB;
    int base = tid * 8;                            // 1024*8 == NB
    int s = 0;
    #pragma unroll
    for (int k = 0; k < 8; k++) s += cnt[base + k];
    ssum[tid] = s;
    __syncthreads();
    for (int d = 1; d < 1024; d <<= 1) {
        int v = (tid >= d) ? ssum[tid - d] : 0;
        __syncthreads();
        ssum[tid] += v;
        __syncthreads();
    }
    int run = (tid == 0) ? 0 : ssum[tid - 1];
    #pragma unroll
    for (int k = 0; k < 8; k++) {
        g_cur[b*NB + base + k] = run;
        run += cnt[base + k];
    }
}

__global__ void __launch_bounds__(256) scatter_kernel(const float* __restrict__ xyz) {
    int t = blockIdx.x * 256 + threadIdx.x;
    int b = t >> 13, i = t & (NN-1);
    const float* p = xyz + ((size_t)b*NN + i)*3;
    float x = p[0], y = p[1], z = p[2];
    int pos = atomicAdd(&g_cur[b*NB + bucketOf(x)], 1);
    g_pts[b*NN + pos] = make_float4(x, y, z, fmaf(z, z, fmaf(y, y, x*x)));
    g_sid[b*NN + pos] = i;
}

// ---------------- KNN: warp-windowed scan over x-sorted stream (exact) ----------------
// NOTE: all top-16 array indexing is STATIC (done-flag match pattern) so d16/i16
// stay in registers. Any dynamic index would demote them to local memory and
// put ~16 LDL/STL on every hot-loop iteration.
__device__ __forceinline__ void insert16(float d, int idx, float* d16, int* i16, float& worst) {
    bool done = false;
    #pragma unroll
    for (int s = 0; s < KNBR; s++)
        if (!done && d16[s] == worst) { d16[s] = d; i16[s] = idx; done = true; }
    worst = d16[0];
    #pragma unroll
    for (int s = 1; s < KNBR; s++) worst = fmaxf(worst, d16[s]);
}

__global__ void __launch_bounds__(64) knn_search_kernel() {
    int t = blockIdx.x * 64 + threadIdx.x;   // global sorted query index
    int b = t >> 13;                         // 32 | 8192 -> warps never straddle batches
    int tq = t & (NN-1);                     // local sorted index
    const float4* __restrict__ pts = g_pts + (size_t)b*NN;
    float4 q = pts[tq];

    float d16[KNBR]; int i16[KNBR];
    #pragma unroll
    for (int i = 0; i < KNBR; i++) { d16[i] = 3.4e38f; i16[i] = 0; }
    float worst = 3.4e38f;

    int t0 = tq & ~31;                       // warp window seed
    int L = t0, R = t0 + 32;

    // scan own block first (includes self: d == 0 exactly)
    #pragma unroll 4
    for (int j = t0; j < t0 + 32; j++) {
        float4 p = pts[j];
        float dot = fmaf(q.z, p.z, fmaf(q.y, p.y, q.x*p.x));
        float d = q.w + p.w - 2.0f * dot;    // same expansion form as reference
        if (d < worst) insert16(d, j, d16, i16, worst);
    }

    // expand window until every lane's top-16 is provably final
    for (;;) {
        bool doneR, doneL;
        if (R < NN) {
            float gap = pts[R].x - BW - q.x;           // uniform (broadcast) load
            doneR = (gap > 0.f) && (gap*gap >= worst);
        } else doneR = true;
        if (L > 0) {
            float gap = q.x - (pts[L-1].x + BW);       // uniform load
            doneL = (gap > 0.f) && (gap*gap >= worst);
        } else doneL = true;

        bool scanR = !__all_sync(0xffffffffu, doneR);
        bool scanL = !__all_sync(0xffffffffu, doneL);
        if (!scanR && !scanL) break;

        if (scanR) {
            int j1 = min(R + 32, NN);
            #pragma unroll 4
            for (int j = R; j < j1; j++) {
                float4 p = pts[j];
                float dot = fmaf(q.z, p.z, fmaf(q.y, p.y, q.x*p.x));
                float d = q.w + p.w - 2.0f * dot;
                if (d < worst) insert16(d, j, d16, i16, worst);
            }
            R = j1;
        }
        if (scanL) {
            int j0 = max(L - 32, 0);
            #pragma unroll 4
            for (int j = j0; j < L; j++) {
                float4 p = pts[j];
                float dot = fmaf(q.z, p.z, fmaf(q.y, p.y, q.x*p.x));
                float d = q.w + p.w - 2.0f * dot;
                if (d < worst) insert16(d, j, d16, i16, worst);
            }
            L = j0;
        }
    }

    // extract 16 smallest using ONLY static indexing (registers preserved)
    int qi = g_sid[(size_t)b*NN + tq];
    size_t ob = ((size_t)(b*NN + qi)) * KNBR;
    #pragma unroll
    for (int m = 0; m < KNBR; m++) {
        float lm = d16[0];
        #pragma unroll
        for (int i = 1; i < KNBR; i++) lm = fminf(lm, d16[i]);
        int sel = 0;
        bool done = false;
        #pragma unroll
        for (int i = 0; i < KNBR; i++) {
            if (!done && d16[i] == lm) { sel = i16[i]; d16[i] = 3.4e38f; done = true; }
        }
        g_knn[ob + m] = g_sid[(size_t)b*NN + sel];
    }
}

// ---------------- K1: projections q,k,v = feats @ W ----------------
#define PROJ_SMEM ((64*132 + 64*64)*4)
__global__ void __launch_bounds__(256) proj_kernel(
    const float* __restrict__ feats,
    const float* __restrict__ wq, const float* __restrict__ wk, const float* __restrict__ wv)
{
    extern __shared__ float sm[];
    float* sFt = sm;            // [64][132] feats^T (k-major)
    float* sW  = sm + 64*132;   // [64][64]
    int tid = threadIdx.x;
    int R0 = blockIdx.x * 128;
    for (int i = tid; i < 128*16; i += 256) {
        int r = i >> 4, c4 = (i & 15) << 2;
        float4 v = *(const float4*)(feats + (size_t)(R0 + r)*64 + c4);
        sFt[(c4+0)*132 + r] = v.x;
        sFt[(c4+1)*132 + r] = v.y;
        sFt[(c4+2)*132 + r] = v.z;
        sFt[(c4+3)*132 + r] = v.w;
    }
    int tm = tid >> 5, tn = tid & 31, c0 = tn * 2;
    int mbase = tm << 4;
    const float* Ws[3] = {wq, wk, wv};
    float* Os[3] = {g_q, g_kf, g_vf};
    for (int mat = 0; mat < 3; mat++) {
        __syncthreads();
        for (int i = tid; i < 1024; i += 256)
            *(float4*)(sW + i*4) = *(const float4*)(Ws[mat] + i*4);
        __syncthreads();
        unsigned long long a0[8], a1[8];
        #pragma unroll
        for (int p = 0; p < 8; p++) { a0[p] = 0ull; a1[p] = 0ull; }
        gemm_f32x2(sFt, sW, mbase, c0, a0, a1);
        float* O = Os[mat];
        #pragma unroll
        for (int p = 0; p < 8; p++) {
            float2 r0 = up2(a0[p]);
            float2 r1 = up2(a1[p]);
            *(float2*)(O + (size_t)(R0 + mbase + 2*p)*64 + c0)   = make_float2(r0.x, r1.x);
            *(float2*)(O + (size_t)(R0 + mbase + 2*p+1)*64 + c0) = make_float2(r0.y, r1.y);
        }
    }
}

// ---------------- K3: mega fused kernel (single reusable weight buffer) ----------------
#define FUSED_SMEM ((64*132 + 64*64 + 192 + 256 + 128)*4)
__global__ void __launch_bounds__(256, 2) fused_kernel(
    const float* __restrict__ xyz, const float* __restrict__ feats,
    const float* __restrict__ w1d, const float* __restrict__ b1d,
    const float* __restrict__ w2d, const float* __restrict__ b2d,
    const float* __restrict__ w1g, const float* __restrict__ b1g,
    const float* __restrict__ w2g, const float* __restrict__ b2g)
{
    extern __shared__ float sm[];
    float* sA   = sm;                 // [64][132]
    float* sW   = sA + 64*132;        // [64][64] (reused for W2d, W1g, W2g)
    float* sW1d = sW + 4096;          // [3][64]
    float* sB   = sW1d + 192;         // b1d|b2d|b1g|b2g
    int*   sIdx = (int*)(sB + 256);   // [128]
    int tid = threadIdx.x;

    for (int i = tid; i < 1024; i += 256)
        *(float4*)(sW + i*4) = *(const float4*)(w2d + i*4);
    if (tid < 192) sW1d[tid] = w1d[tid];
    if (tid < 64) { sB[tid] = b1d[tid]; sB[64+tid] = b2d[tid]; sB[128+tid] = b1g[tid]; sB[192+tid] = b2g[tid]; }

    int R0 = blockIdx.x * 128;
    int P0 = blockIdx.x * 8;
    int b  = P0 >> 13;
    __syncthreads();

    // ---- stage H1 = relu(dxyz @ W1d + b1d) into sA (k-major) ----
    {
        int m   = tid >> 1;
        int row = R0 + m;
        int pn  = row >> 4;
        int nl  = pn & (NN - 1);
        int j   = g_knn[row];
        if ((tid & 1) == 0) sIdx[m] = j;
        const float* xb = xyz + (size_t)b * NN * 3;
        float dx = xb[nl*3+0] - xb[j*3+0];
        float dy = xb[nl*3+1] - xb[j*3+1];
        float dz = xb[nl*3+2] - xb[j*3+2];
        int cb = (tid & 1) * 32;
        #pragma unroll 8
        for (int c = 0; c < 32; c++) {
            int cc = cb + c;
            float h = fmaf(dz, sW1d[128+cc], fmaf(dy, sW1d[64+cc], fmaf(dx, sW1d[cc], sB[cc])));
            sA[cc*132 + m] = fmaxf(h, 0.f);
        }
    }
    __syncthreads();

    int tm = tid >> 5, tn = tid & 31, c0 = tn * 2;
    int mbase = tm << 4;
    int pn0 = P0 + tm;

    // ---- GEMM1: pos = H1 @ W2d + b2d ----
    unsigned long long a0[8], a1[8];
    {
        unsigned long long bb0 = pk2(sB[64+c0],   sB[64+c0]);
        unsigned long long bb1 = pk2(sB[64+c0+1], sB[64+c0+1]);
        #pragma unroll
        for (int p = 0; p < 8; p++) { a0[p] = bb0; a1[p] = bb1; }
        gemm_f32x2(sA, sW, mbase, c0, a0, a1);
    }
    __syncthreads();   // done reading H1 (sA) and W2d (sW)

    // ---- epilogue: x = q - kf + pos -> sA ; val = vf + pos -> v0/v1 ; load W1g ----
    float v0[KNBR], v1[KNBR];
    {
        float2 qv = *(const float2*)(g_q + (size_t)pn0*64 + c0);
        #pragma unroll
        for (int p = 0; p < 8; p++) {
            float2 ps0 = up2(a0[p]);
            float2 ps1 = up2(a1[p]);
            int j0 = sIdx[mbase + 2*p];
            int j1 = sIdx[mbase + 2*p + 1];
            size_t gp0 = ((size_t)(b*NN + j0))*64 + c0;
            size_t gp1 = ((size_t)(b*NN + j1))*64 + c0;
            float2 kf0 = *(const float2*)(g_kf + gp0);
            float2 kf1 = *(const float2*)(g_kf + gp1);
            float2 vf0 = *(const float2*)(g_vf + gp0);
            float2 vf1 = *(const float2*)(g_vf + gp1);
            v0[2*p]   = vf0.x + ps0.x;  v1[2*p]   = vf0.y + ps1.x;
            v0[2*p+1] = vf1.x + ps0.y;  v1[2*p+1] = vf1.y + ps1.y;
            *(float2*)(sA + c0*132     + mbase + 2*p) = make_float2(qv.x - kf0.x + ps0.x, qv.x - kf1.x + ps0.y);
            *(float2*)(sA + (c0+1)*132 + mbase + 2*p) = make_float2(qv.y - kf0.y + ps1.x, qv.y - kf1.y + ps1.y);
        }
        for (int i = tid; i < 1024; i += 256)
            *(float4*)(sW + i*4) = *(const float4*)(w1g + i*4);
    }
    __syncthreads();

    // ---- GEMM2: g1 = relu(x @ W1g + b1g) ----
    {
        unsigned long long bb0 = pk2(sB[128+c0],   sB[128+c0]);
        unsigned long long bb1 = pk2(sB[128+c0+1], sB[128+c0+1]);
        #pragma unroll
        for (int p = 0; p < 8; p++) { a0[p] = bb0; a1[p] = bb1; }
        gemm_f32x2(sA, sW, mbase, c0, a0, a1);
    }
    __syncthreads();   // done reading x (sA) and W1g (sW)
    #pragma unroll
    for (int p = 0; p < 8; p++) {
        float2 r0 = up2(a0[p]), r1 = up2(a1[p]);
        *(float2*)(sA + c0*132     + mbase + 2*p) = make_float2(fmaxf(r0.x,0.f), fmaxf(r0.y,0.f));
        *(float2*)(sA + (c0+1)*132 + mbase + 2*p) = make_float2(fmaxf(r1.x,0.f), fmaxf(r1.y,0.f));
    }
    for (int i = tid; i < 1024; i += 256)
        *(float4*)(sW + i*4) = *(const float4*)(w2g + i*4);
    __syncthreads();

    // ---- GEMM3: logits = g1 @ W2g + b2g ----
    {
        unsigned long long bb0 = pk2(sB[192+c0],   sB[192+c0]);
        unsigned long long bb1 = pk2(sB[192+c0+1], sB[192+c0+1]);
        #pragma unroll
        for (int p = 0; p < 8; p++) { a0[p] = bb0; a1[p] = bb1; }
        gemm_f32x2(sA, sW, mbase, c0, a0, a1);
    }

    // ---- softmax over K (thread-local) + weighted sum + residual ----
    float t0a[KNBR], t1a[KNBR];
    #pragma unroll
    for (int p = 0; p < 8; p++) {
        float2 r0 = up2(a0[p]), r1 = up2(a1[p]);
        t0a[2*p] = r0.x; t0a[2*p+1] = r0.y;
        t1a[2*p] = r1.x; t1a[2*p+1] = r1.y;
    }
    float m0 = t0a[0], m1 = t1a[0];
    #pragma unroll
    for (int s = 1; s < KNBR; s++) { m0 = fmaxf(m0, t0a[s]); m1 = fmaxf(m1, t1a[s]); }
    float s0 = 0.f, s1 = 0.f;
    #pragma unroll
    for (int s = 0; s < KNBR; s++) {
        t0a[s] = __expf(t0a[s] - m0);  s0 += t0a[s];
        t1a[s] = __expf(t1a[s] - m1);  s1 += t1a[s];
    }
    float r0 = 0.f, r1 = 0.f;
    #pragma unroll
    for (int s = 0; s < KNBR; s++) { r0 = fmaf(t0a[s], v0[s], r0); r1 = fmaf(t1a[s], v1[s], r1); }
    float2 fv = *(const float2*)(feats + (size_t)pn0*64 + c0);
    r0 = r0 / s0 + fv.x;
    r1 = r1 / s1 + fv.y;
    *(float2*)(g_res + (size_t)pn0*64 + c0) = make_float2(r0, r1);

    // ---- BN partial sums ----
    __syncthreads();
    if (tid < 128) sA[tid] = 0.f;
    __syncthreads();
    atomicAdd(&sA[c0],      r0);
    atomicAdd(&sA[c0+1],    r1);
    atomicAdd(&sA[64+c0],   r0*r0);
    atomicAdd(&sA[64+c0+1], r1*r1);
    __syncthreads();
    if (tid < 64) {
        atomicAdd(&g_sum[tid],   sA[tid]);
        atomicAdd(&g_sumsq[tid], sA[64+tid]);
    }
}

// ---------------- K4: BatchNorm apply ----------------
__global__ void __launch_bounds__(256) bn_kernel(
    const float* __restrict__ bn_gamma, const float* __restrict__ bn_beta,
    float* __restrict__ out)
{
    int idx = blockIdx.x * 256 + threadIdx.x;
    int c = idx & 63;
    float inv = 1.0f / (float)NPTS;
    float mean = g_sum[c] * inv;
    float var  = g_sumsq[c] * inv - mean * mean;
    out[idx] = (g_res[idx] - mean) * rsqrtf(var + 1e-5f) * bn_gamma[c] + bn_beta[c];
}

// ---------------- launch ----------------
extern "C" void kernel_launch(void* const* d_in, const int* in_sizes, int n_in,
                              void* d_out, int out_size)
{
    const float* xyz   = (const float*)d_in[0];
    const float* feats = (const float*)d_in[1];
    const float* wq    = (const float*)d_in[2];
    const float* wk    = (const float*)d_in[3];
    const float* wv    = (const float*)d_in[4];
    const float* dw1   = (const float*)d_in[5];
    const float* db1   = (const float*)d_in[6];
    const float* dw2   = (const float*)d_in[7];
    const float* db2   = (const float*)d_in[8];
    const float* gw1   = (const float*)d_in[9];
    const float* gb1   = (const float*)d_in[10];
    const float* gw2   = (const float*)d_in[11];
    const float* gb2   = (const float*)d_in[12];
    const float* bng   = (const float*)d_in[13];
    const float* bnb   = (const float*)d_in[14];
    float* out = (float*)d_out;

    cudaFuncSetAttribute(proj_kernel,  cudaFuncAttributeMaxDynamicSharedMemorySize, PROJ_SMEM);
    cudaFuncSetAttribute(fused_kernel, cudaFuncAttributeMaxDynamicSharedMemorySize, FUSED_SMEM);

    zero_kernel      <<<(BB*NB)/1024, 1024>>>();
    count_kernel     <<<NPTS/256, 256>>>(xyz);
    scan_kernel      <<<BB, 1024>>>();
    scatter_kernel   <<<NPTS/256, 256>>>(xyz);
    knn_search_kernel<<<NPTS/64, 64>>>();     // warp = 32 x-adjacent queries, windowed scan
    proj_kernel      <<<128, 256, PROJ_SMEM>>>(feats, wq, wk, wv);
    fused_kernel     <<<2048, 256, FUSED_SMEM>>>(xyz, feats, dw1, db1, dw2, db2, gw1, gb1, gw2, gb2);
    bn_kernel        <<<4096, 256>>>(bng, bnb, out);
}

// round 12
// speedup vs baseline: 3.6608x; 1.2152x over previous
#include <cuda_runtime.h>
#include <math.h>

#define BB 2
#define NN 8192
#define DD 64
#define KNBR 16
#define NPTS (BB*NN)          // 16384
#define ROWS (NPTS*KNBR)      // 262144

// ---- 1-D x-bucket sort for KNN ----
#define NB   8192
#define XLO  (-9.0f)
#define XRNG 18.0f
#define BW   (XRNG/NB)        // 0.0021973
#define INVBW ((float)NB/XRNG)

// ---------------- scratch (static device arrays; no allocation) ----------------
__device__ float  g_q  [NPTS*DD];
__device__ float  g_kf [NPTS*DD];
__device__ float  g_vf [NPTS*DD];
__device__ int    g_knn[ROWS];
__device__ float  g_res[NPTS*DD];
__device__ float  g_sum[DD];
__device__ float  g_sumsq[DD];
__device__ int    g_cnt  [BB*NB];
__device__ float4 g_pts  [NPTS];     // x-bucket-sorted (x,y,z,|p|^2) per batch
__device__ int    g_sid  [NPTS];     // original index of sorted point

// ---------------- packed f32x2 helpers ----------------
__device__ __forceinline__ void fma2(unsigned long long &d, unsigned long long a, unsigned long long b) {
    asm("fma.rn.f32x2 %0, %1, %2, %0;" : "+l"(d) : "l"(a), "l"(b));
}
__device__ __forceinline__ unsigned long long pk2(float lo, float hi) {
    unsigned long long r; asm("mov.b64 %0, {%1,%2};" : "=l"(r) : "f"(lo), "f"(hi)); return r;
}
__device__ __forceinline__ float2 up2(unsigned long long v) {
    float2 r; asm("mov.b64 {%0,%1}, %2;" : "=f"(r.x), "=f"(r.y) : "l"(v)); return r;
}

// 128x64 GEMM slice. sA: k-major [64][132]; sW: row-major [64][64].
__device__ __forceinline__ void gemm_f32x2(const float* __restrict__ sA, const float* __restrict__ sW,
                                           int mbase, int c0,
                                           unsigned long long* a0, unsigned long long* a1)
{
    #pragma unroll 4
    for (int kk = 0; kk < 64; kk++) {
        const ulonglong2* ap = (const ulonglong2*)(sA + kk*132 + mbase);   // broadcast LDS.128
        float2 w = *(const float2*)(sW + kk*64 + c0);                      // LDS.64
        unsigned long long w0 = pk2(w.x, w.x);
        unsigned long long w1 = pk2(w.y, w.y);
        ulonglong2 A0 = ap[0], A1 = ap[1];
        fma2(a0[0], A0.x, w0); fma2(a1[0], A0.x, w1);
        fma2(a0[1], A0.y, w0); fma2(a1[1], A0.y, w1);
        fma2(a0[2], A1.x, w0); fma2(a1[2], A1.x, w1);
        fma2(a0[3], A1.y, w0); fma2(a1[3], A1.y, w1);
        ulonglong2 A2 = ap[2], A3 = ap[3];
        fma2(a0[4], A2.x, w0); fma2(a1[4], A2.x, w1);
        fma2(a0[5], A2.y, w0); fma2(a1[5], A2.y, w1);
        fma2(a0[6], A3.x, w0); fma2(a1[6], A3.x, w1);
        fma2(a0[7], A3.y, w0); fma2(a1[7], A3.y, w1);
    }
}

// ---------------- bucket sort build ----------------
__device__ __forceinline__ int bucketOf(float x) {
    int c = (int)((x - XLO) * INVBW);
    return min(max(c, 0), NB-1);
}

__global__ void __launch_bounds__(1024) zero_kernel() {
    int i = blockIdx.x * 1024 + threadIdx.x;       // 16*1024 == BB*NB
    g_cnt[i] = 0;
    if (i < 64) { g_sum[i] = 0.f; g_sumsq[i] = 0.f; }
}

__global__ void __launch_bounds__(256) count_kernel(const float* __restrict__ xyz) {
    int t = blockIdx.x * 256 + threadIdx.x;        // 64*256 == NPTS
    int b = t >> 13, i = t & (NN-1);
    atomicAdd(&g_cnt[b*NB + bucketOf(xyz[((size_t)b*NN + i)*3])], 1);
}

// prefix over NB buckets AND scatter, one block per batch (smem cursors)
__global__ void __launch_bounds__(1024) scan_scatter_kernel(const float* __restrict__ xyz) {
    __shared__ int ssum[1024];
    __shared__ int cur[NB];                        // 32 KB
    int b = blockIdx.x, tid = threadIdx.x;
    const int* cnt = g_cnt + b*NB;
    int base = tid * 8;                            // 1024*8 == NB
    int loc[8];
    int s = 0;
    #pragma unroll
    for (int k = 0; k < 8; k++) { loc[k] = cnt[base + k]; s += loc[k]; }
    ssum[tid] = s;
    __syncthreads();
    for (int d = 1; d < 1024; d <<= 1) {
        int v = (tid >= d) ? ssum[tid - d] : 0;
        __syncthreads();
        ssum[tid] += v;
        __syncthreads();
    }
    int run = (tid == 0) ? 0 : ssum[tid - 1];
    #pragma unroll
    for (int k = 0; k < 8; k++) { cur[base + k] = run; run += loc[k]; }
    __syncthreads();
    // scatter this batch's points
    for (int i = tid; i < NN; i += 1024) {
        const float* p = xyz + ((size_t)b*NN + i)*3;
        float x = p[0], y = p[1], z = p[2];
        int pos = atomicAdd(&cur[bucketOf(x)], 1);
        g_pts[b*NN + pos] = make_float4(x, y, z, fmaf(z, z, fmaf(y, y, x*x)));
        g_sid[b*NN + pos] = i;
    }
}

// ---------------- KNN: warp-windowed scan over x-sorted stream (exact) ----------------
// All top-16 indexing is STATIC so d16/i16 stay in registers.
__device__ __forceinline__ void insert16(float d, int idx, float* d16, int* i16, float& worst) {
    bool done = false;
    #pragma unroll
    for (int s = 0; s < KNBR; s++)
        if (!done && d16[s] == worst) { d16[s] = d; i16[s] = idx; done = true; }
    worst = d16[0];
    #pragma unroll
    for (int s = 1; s < KNBR; s++) worst = fmaxf(worst, d16[s]);
}

// scan [j0,j1): 4 independent loads batched ahead of the serial compare chain
__device__ __forceinline__ void scanChunk(const float4* __restrict__ pts, int j0, int j1,
                                          float4 q, float* d16, int* i16, float& worst) {
    int j = j0;
    for (; j + 4 <= j1; j += 4) {
        float4 p0 = pts[j], p1 = pts[j+1], p2 = pts[j+2], p3 = pts[j+3];
        float dd0 = q.w + p0.w - 2.0f * fmaf(q.z, p0.z, fmaf(q.y, p0.y, q.x*p0.x));
        float dd1 = q.w + p1.w - 2.0f * fmaf(q.z, p1.z, fmaf(q.y, p1.y, q.x*p1.x));
        float dd2 = q.w + p2.w - 2.0f * fmaf(q.z, p2.z, fmaf(q.y, p2.y, q.x*p2.x));
        float dd3 = q.w + p3.w - 2.0f * fmaf(q.z, p3.z, fmaf(q.y, p3.y, q.x*p3.x));
        if (dd0 < worst) insert16(dd0, j,   d16, i16, worst);
        if (dd1 < worst) insert16(dd1, j+1, d16, i16, worst);
        if (dd2 < worst) insert16(dd2, j+2, d16, i16, worst);
        if (dd3 < worst) insert16(dd3, j+3, d16, i16, worst);
    }
    for (; j < j1; j++) {
        float4 p = pts[j];
        float d = q.w + p.w - 2.0f * fmaf(q.z, p.z, fmaf(q.y, p.y, q.x*p.x));
        if (d < worst) insert16(d, j, d16, i16, worst);
    }
}

__global__ void __launch_bounds__(64) knn_search_kernel() {
    int t = blockIdx.x * 64 + threadIdx.x;   // global sorted query index
    int b = t >> 13;                         // 32 | 8192 -> warps never straddle batches
    int tq = t & (NN-1);                     // local sorted index
    const float4* __restrict__ pts = g_pts + (size_t)b*NN;
    float4 q = pts[tq];

    float d16[KNBR]; int i16[KNBR];
    #pragma unroll
    for (int i = 0; i < KNBR; i++) { d16[i] = 3.4e38f; i16[i] = 0; }
    float worst = 3.4e38f;

    int t0 = tq & ~31;                       // warp window seed
    int L = t0, R = t0 + 32;

    // scan own block first (includes self: d == 0 exactly)
    scanChunk(pts, t0, t0 + 32, q, d16, i16, worst);

    // expand window until every lane's top-16 is provably final (64/side per check)
    for (;;) {
        bool doneR, doneL;
        if (R < NN) {
            float gap = pts[R].x - BW - q.x;           // uniform (broadcast) load
            doneR = (gap > 0.f) && (gap*gap >= worst);
        } else doneR = true;
        if (L > 0) {
            float gap = q.x - (pts[L-1].x + BW);       // uniform load
            doneL = (gap > 0.f) && (gap*gap >= worst);
        } else doneL = true;

        bool scanR = !__all_sync(0xffffffffu, doneR);
        bool scanL = !__all_sync(0xffffffffu, doneL);
        if (!scanR && !scanL) break;

        if (scanR) {
            int j1 = min(R + 64, NN);
            scanChunk(pts, R, j1, q, d16, i16, worst);
            R = j1;
        }
        if (scanL) {
            int j0 = max(L - 64, 0);
            scanChunk(pts, j0, L, q, d16, i16, worst);
            L = j0;
        }
    }

    // extract 16 smallest using ONLY static indexing (registers preserved)
    int qi = g_sid[(size_t)b*NN + tq];
    size_t ob = ((size_t)(b*NN + qi)) * KNBR;
    #pragma unroll
    for (int m = 0; m < KNBR; m++) {
        float lm = d16[0];
        #pragma unroll
        for (int i = 1; i < KNBR; i++) lm = fminf(lm, d16[i]);
        int sel = 0;
        bool done = false;
        #pragma unroll
        for (int i = 0; i < KNBR; i++) {
            if (!done && d16[i] == lm) { sel = i16[i]; d16[i] = 3.4e38f; done = true; }
        }
        g_knn[ob + m] = g_sid[(size_t)b*NN + sel];
    }
}

// ---------------- K1: projections q,k,v = feats @ W ----------------
#define PROJ_SMEM ((64*132 + 64*64)*4)
__global__ void __launch_bounds__(256) proj_kernel(
    const float* __restrict__ feats,
    const float* __restrict__ wq, const float* __restrict__ wk, const float* __restrict__ wv)
{
    extern __shared__ float sm[];
    float* sFt = sm;            // [64][132] feats^T (k-major)
    float* sW  = sm + 64*132;   // [64][64]
    int tid = threadIdx.x;
    int R0 = blockIdx.x * 128;
    for (int i = tid; i < 128*16; i += 256) {
        int r = i >> 4, c4 = (i & 15) << 2;
        float4 v = *(const float4*)(feats + (size_t)(R0 + r)*64 + c4);
        sFt[(c4+0)*132 + r] = v.x;
        sFt[(c4+1)*132 + r] = v.y;
        sFt[(c4+2)*132 + r] = v.z;
        sFt[(c4+3)*132 + r] = v.w;
    }
    int tm = tid >> 5, tn = tid & 31, c0 = tn * 2;
    int mbase = tm << 4;
    const float* Ws[3] = {wq, wk, wv};
    float* Os[3] = {g_q, g_kf, g_vf};
    for (int mat = 0; mat < 3; mat++) {
        __syncthreads();
        for (int i = tid; i < 1024; i += 256)
            *(float4*)(sW + i*4) = *(const float4*)(Ws[mat] + i*4);
        __syncthreads();
        unsigned long long a0[8], a1[8];
        #pragma unroll
        for (int p = 0; p < 8; p++) { a0[p] = 0ull; a1[p] = 0ull; }
        gemm_f32x2(sFt, sW, mbase, c0, a0, a1);
        float* O = Os[mat];
        #pragma unroll
        for (int p = 0; p < 8; p++) {
            float2 r0 = up2(a0[p]);
            float2 r1 = up2(a1[p]);
            *(float2*)(O + (size_t)(R0 + mbase + 2*p)*64 + c0)   = make_float2(r0.x, r1.x);
            *(float2*)(O + (size_t)(R0 + mbase + 2*p+1)*64 + c0) = make_float2(r0.y, r1.y);
        }
    }
}

// ---------------- K3: mega fused kernel (single reusable weight buffer) ----------------
#define FUSED_SMEM ((64*132 + 64*64 + 192 + 256 + 128)*4)
__global__ void __launch_bounds__(256, 2) fused_kernel(
    const float* __restrict__ xyz, const float* __restrict__ feats,
    const float* __restrict__ w1d, const float* __restrict__ b1d,
    const float* __restrict__ w2d, const float* __restrict__ b2d,
    const float* __restrict__ w1g, const float* __restrict__ b1g,
    const float* __restrict__ w2g, const float* __restrict__ b2g)
{
    extern __shared__ float sm[];
    float* sA   = sm;                 // [64][132]
    float* sW   = sA + 64*132;        // [64][64] (reused for W2d, W1g, W2g)
    float* sW1d = sW + 4096;          // [3][64]
    float* sB   = sW1d + 192;         // b1d|b2d|b1g|b2g
    int*   sIdx = (int*)(sB + 256);   // [128]
    int tid = threadIdx.x;

    for (int i = tid; i < 1024; i += 256)
        *(float4*)(sW + i*4) = *(const float4*)(w2d + i*4);
    if (tid < 192) sW1d[tid] = w1d[tid];
    if (tid < 64) { sB[tid] = b1d[tid]; sB[64+tid] = b2d[tid]; sB[128+tid] = b1g[tid]; sB[192+tid] = b2g[tid]; }

    int R0 = blockIdx.x * 128;
    int P0 = blockIdx.x * 8;
    int b  = P0 >> 13;
    __syncthreads();

    // ---- stage H1 = relu(dxyz @ W1d + b1d) into sA (k-major) ----
    {
        int m   = tid >> 1;
        int row = R0 + m;
        int pn  = row >> 4;
        int nl  = pn & (NN - 1);
        int j   = g_knn[row];
        if ((tid & 1) == 0) sIdx[m] = j;
        const float* xb = xyz + (size_t)b * NN * 3;
        float dx = xb[nl*3+0] - xb[j*3+0];
        float dy = xb[nl*3+1] - xb[j*3+1];
        float dz = xb[nl*3+2] - xb[j*3+2];
        int cb = (tid & 1) * 32;
        #pragma unroll 8
        for (int c = 0; c < 32; c++) {
            int cc = cb + c;
            float h = fmaf(dz, sW1d[128+cc], fmaf(dy, sW1d[64+cc], fmaf(dx, sW1d[cc], sB[cc])));
            sA[cc*132 + m] = fmaxf(h, 0.f);
        }
    }
    __syncthreads();

    int tm = tid >> 5, tn = tid & 31, c0 = tn * 2;
    int mbase = tm << 4;
    int pn0 = P0 + tm;

    // ---- GEMM1: pos = H1 @ W2d + b2d ----
    unsigned long long a0[8], a1[8];
    {
        unsigned long long bb0 = pk2(sB[64+c0],   sB[64+c0]);
        unsigned long long bb1 = pk2(sB[64+c0+1], sB[64+c0+1]);
        #pragma unroll
        for (int p = 0; p < 8; p++) { a0[p] = bb0; a1[p] = bb1; }
        gemm_f32x2(sA, sW, mbase, c0, a0, a1);
    }
    __syncthreads();   // done reading H1 (sA) and W2d (sW)

    // ---- epilogue: x = q - kf + pos -> sA ; val = vf + pos -> v0/v1 ; load W1g ----
    float v0[KNBR], v1[KNBR];
    {
        float2 qv = *(const float2*)(g_q + (size_t)pn0*64 + c0);
        #pragma unroll
        for (int p = 0; p < 8; p++) {
            float2 ps0 = up2(a0[p]);
            float2 ps1 = up2(a1[p]);
            int j0 = sIdx[mbase + 2*p];
            int j1 = sIdx[mbase + 2*p + 1];
            size_t gp0 = ((size_t)(b*NN + j0))*64 + c0;
            size_t gp1 = ((size_t)(b*NN + j1))*64 + c0;
            float2 kf0 = *(const float2*)(g_kf + gp0);
            float2 kf1 = *(const float2*)(g_kf + gp1);
            float2 vf0 = *(const float2*)(g_vf + gp0);
            float2 vf1 = *(const float2*)(g_vf + gp1);
            v0[2*p]   = vf0.x + ps0.x;  v1[2*p]   = vf0.y + ps1.x;
            v0[2*p+1] = vf1.x + ps0.y;  v1[2*p+1] = vf1.y + ps1.y;
            *(float2*)(sA + c0*132     + mbase + 2*p) = make_float2(qv.x - kf0.x + ps0.x, qv.x - kf1.x + ps0.y);
            *(float2*)(sA + (c0+1)*132 + mbase + 2*p) = make_float2(qv.y - kf0.y + ps1.x, qv.y - kf1.y + ps1.y);
        }
        for (int i = tid; i < 1024; i += 256)
            *(float4*)(sW + i*4) = *(const float4*)(w1g + i*4);
    }
    __syncthreads();

    // ---- GEMM2: g1 = relu(x @ W1g + b1g) ----
    {
        unsigned long long bb0 = pk2(sB[128+c0],   sB[128+c0]);
        unsigned long long bb1 = pk2(sB[128+c0+1], sB[128+c0+1]);
        #pragma unroll
        for (int p = 0; p < 8; p++) { a0[p] = bb0; a1[p] = bb1; }
        gemm_f32x2(sA, sW, mbase, c0, a0, a1);
    }
    __syncthreads();   // done reading x (sA) and W1g (sW)
    #pragma unroll
    for (int p = 0; p < 8; p++) {
        float2 r0 = up2(a0[p]), r1 = up2(a1[p]);
        *(float2*)(sA + c0*132     + mbase + 2*p) = make_float2(fmaxf(r0.x,0.f), fmaxf(r0.y,0.f));
        *(float2*)(sA + (c0+1)*132 + mbase + 2*p) = make_float2(fmaxf(r1.x,0.f), fmaxf(r1.y,0.f));
    }
    for (int i = tid; i < 1024; i += 256)
        *(float4*)(sW + i*4) = *(const float4*)(w2g + i*4);
    __syncthreads();

    // ---- GEMM3: logits = g1 @ W2g + b2g ----
    {
        unsigned long long bb0 = pk2(sB[192+c0],   sB[192+c0]);
        unsigned long long bb1 = pk2(sB[192+c0+1], sB[192+c0+1]);
        #pragma unroll
        for (int p = 0; p < 8; p++) { a0[p] = bb0; a1[p] = bb1; }
        gemm_f32x2(sA, sW, mbase, c0, a0, a1);
    }

    // ---- softmax over K (thread-local) + weighted sum + residual ----
    float t0a[KNBR], t1a[KNBR];
    #pragma unroll
    for (int p = 0; p < 8; p++) {
        float2 r0 = up2(a0[p]), r1 = up2(a1[p]);
        t0a[2*p] = r0.x; t0a[2*p+1] = r0.y;
        t1a[2*p] = r1.x; t1a[2*p+1] = r1.y;
    }
    float m0 = t0a[0], m1 = t1a[0];
    #pragma unroll
    for (int s = 1; s < KNBR; s++) { m0 = fmaxf(m0, t0a[s]); m1 = fmaxf(m1, t1a[s]); }
    float s0 = 0.f, s1 = 0.f;
    #pragma unroll
    for (int s = 0; s < KNBR; s++) {
        t0a[s] = __expf(t0a[s] - m0);  s0 += t0a[s];
        t1a[s] = __expf(t1a[s] - m1);  s1 += t1a[s];
    }
    float r0 = 0.f, r1 = 0.f;
    #pragma unroll
    for (int s = 0; s < KNBR; s++) { r0 = fmaf(t0a[s], v0[s], r0); r1 = fmaf(t1a[s], v1[s], r1); }
    float2 fv = *(const float2*)(feats + (size_t)pn0*64 + c0);
    r0 = r0 / s0 + fv.x;
    r1 = r1 / s1 + fv.y;
    *(float2*)(g_res + (size_t)pn0*64 + c0) = make_float2(r0, r1);

    // ---- BN partial sums ----
    __syncthreads();
    if (tid < 128) sA[tid] = 0.f;
    __syncthreads();
    atomicAdd(&sA[c0],      r0);
    atomicAdd(&sA[c0+1],    r1);
    atomicAdd(&sA[64+c0],   r0*r0);
    atomicAdd(&sA[64+c0+1], r1*r1);
    __syncthreads();
    if (tid < 64) {
        atomicAdd(&g_sum[tid],   sA[tid]);
        atomicAdd(&g_sumsq[tid], sA[64+tid]);
    }
}

// ---------------- K4: BatchNorm apply ----------------
__global__ void __launch_bounds__(256) bn_kernel(
    const float* __restrict__ bn_gamma, const float* __restrict__ bn_beta,
    float* __restrict__ out)
{
    int idx = blockIdx.x * 256 + threadIdx.x;
    int c = idx & 63;
    float inv = 1.0f / (float)NPTS;
    float mean = g_sum[c] * inv;
    float var  = g_sumsq[c] * inv - mean * mean;
    out[idx] = (g_res[idx] - mean) * rsqrtf(var + 1e-5f) * bn_gamma[c] + bn_beta[c];
}

// ---------------- launch ----------------
extern "C" void kernel_launch(void* const* d_in, const int* in_sizes, int n_in,
                              void* d_out, int out_size)
{
    const float* xyz   = (const float*)d_in[0];
    const float* feats = (const float*)d_in[1];
    const float* wq    = (const float*)d_in[2];
    const float* wk    = (const float*)d_in[3];
    const float* wv    = (const float*)d_in[4];
    const float* dw1   = (const float*)d_in[5];
    const float* db1   = (const float*)d_in[6];
    const float* dw2   = (const float*)d_in[7];
    const float* db2   = (const float*)d_in[8];
    const float* gw1   = (const float*)d_in[9];
    const float* gb1   = (const float*)d_in[10];
    const float* gw2   = (const float*)d_in[11];
    const float* gb2   = (const float*)d_in[12];
    const float* bng   = (const float*)d_in[13];
    const float* bnb   = (const float*)d_in[14];
    float* out = (float*)d_out;

    cudaFuncSetAttribute(proj_kernel,  cudaFuncAttributeMaxDynamicSharedMemorySize, PROJ_SMEM);
    cudaFuncSetAttribute(fused_kernel, cudaFuncAttributeMaxDynamicSharedMemorySize, FUSED_SMEM);

    zero_kernel        <<<(BB*NB)/1024, 1024>>>();          // launch 0
    count_kernel       <<<NPTS/256, 256>>>(xyz);            // launch 1
    scan_scatter_kernel<<<BB, 1024>>>(xyz);                 // launch 2
    knn_search_kernel  <<<NPTS/64, 64>>>();                 // launch 3  <- ncu capture slot
    proj_kernel        <<<128, 256, PROJ_SMEM>>>(feats, wq, wk, wv);
    fused_kernel       <<<2048, 256, FUSED_SMEM>>>(xyz, feats, dw1, db1, dw2, db2, gw1, gb1, gw2, gb2);
    bn_kernel          <<<4096, 256>>>(bng, bnb, out);
}